// round 1
// baseline (speedup 1.0000x reference)
#include <cuda_runtime.h>

// Problem constants
#define Bq     8
#define NIN    512
#define NOUT   1024
#define Cc     16
#define OUTC   32
#define KW     5

// Gauss kernel tiling
#define NSPLIT 4
#define NCHUNK (NIN / NSPLIT)   // 128
#define MTILE  128
#define MT     (NOUT / MTILE)   // 8
#define DTHREADS 128

// Scratch (no runtime allocation allowed)
__device__ float g_rt[Bq * NIN * Cc];            // conv output, layout [b][n][c]
__device__ float g_zp[Bq * NOUT * NSPLIT * Cc];  // partial z, layout [b][m][s][c]

// ---------------------------------------------------------------------------
// Kernel A: Conv1d (NCH, OIH, SAME pad=2) + bias, transposed output [b][n][c]
// grid (4, B), block 128: each block does 128 n positions of one batch b.
// ---------------------------------------------------------------------------
__global__ void conv_kernel(const float* __restrict__ r,
                            const float* __restrict__ w,
                            const float* __restrict__ bias) {
    __shared__ float sh_r[Cc][NIN];        // 32 KB
    __shared__ float sh_w[Cc][Cc][KW];     // 5 KB
    __shared__ float sh_b[Cc];

    const int b = blockIdx.y;
    const int t = threadIdx.x;

    const float4* rb4 = reinterpret_cast<const float4*>(r + (size_t)b * Cc * NIN);
    float4* shr4 = reinterpret_cast<float4*>(&sh_r[0][0]);
    #pragma unroll
    for (int i = t; i < Cc * NIN / 4; i += DTHREADS) shr4[i] = rb4[i];
    for (int i = t; i < Cc * Cc * KW; i += DTHREADS) (&sh_w[0][0][0])[i] = w[i];
    if (t < Cc) sh_b[t] = bias[t];
    __syncthreads();

    const int n = blockIdx.x * DTHREADS + t;

    float acc[Cc];
    #pragma unroll
    for (int c = 0; c < Cc; c++) acc[c] = sh_b[c];

    #pragma unroll
    for (int k = 0; k < KW; k++) {
        int idx = n + k - 2;
        if (idx >= 0 && idx < NIN) {
            #pragma unroll
            for (int ci = 0; ci < Cc; ci++) {
                float v = sh_r[ci][idx];
                #pragma unroll
                for (int c = 0; c < Cc; c++) acc[c] += v * sh_w[c][ci][k];
            }
        }
    }

    float* outp = g_rt + ((size_t)b * NIN + n) * Cc;
    #pragma unroll
    for (int c = 0; c < Cc; c += 4)
        *reinterpret_cast<float4*>(outp + c) =
            make_float4(acc[c], acc[c + 1], acc[c + 2], acc[c + 3]);
}

// ---------------------------------------------------------------------------
// Kernel D: Gaussian transform partials.
// grid (MT, NSPLIT, B), block 128. Block (mt, s, b) processes m-tile of 128
// targets against n-chunk of 128 contexts; writes partial z to g_zp.
// Fast path when all sigma identical: one exp per (n,m) pair.
// ---------------------------------------------------------------------------
__global__ void gauss_kernel(const float* __restrict__ xc,
                             const float* __restrict__ xt,
                             const float* __restrict__ sigma) {
    __shared__ float shx[NCHUNK];            // context x chunk
    __shared__ float shrt[NCHUNK][Cc];       // conv-output chunk (8 KB)
    __shared__ float sh_nh[Cc];              // -0.5 / s_c^2
    __shared__ int   sh_alleq;

    const int b  = blockIdx.z;
    const int s  = blockIdx.y;
    const int mt = blockIdx.x;
    const int t  = threadIdx.x;

    if (t < Cc) {
        float sg = sigma[t];
        sh_nh[t] = -0.5f * expf(-2.0f * sg);   // natural-log coefficient
    }
    if (t == 0) {
        float s0 = sigma[0];
        int eq = 1;
        #pragma unroll
        for (int c = 1; c < Cc; c++) eq &= (sigma[c] == s0);
        sh_alleq = eq;
    }

    const int n0 = s * NCHUNK;
    // load context x chunk
    if (t < NCHUNK) shx[t] = xc[(size_t)b * NIN + n0 + t];
    // load conv output chunk [NCHUNK][Cc] (contiguous)
    {
        const float4* src = reinterpret_cast<const float4*>(
            g_rt + ((size_t)b * NIN + n0) * Cc);
        float4* dst = reinterpret_cast<float4*>(&shrt[0][0]);
        #pragma unroll
        for (int i = t; i < NCHUNK * Cc / 4; i += DTHREADS) dst[i] = src[i];
    }
    __syncthreads();

    const int m = mt * MTILE + t;
    const float xm = xt[(size_t)b * NOUT + m];

    float acc[Cc];
    #pragma unroll
    for (int c = 0; c < Cc; c++) acc[c] = 0.0f;

    if (sh_alleq) {
        // fast path: channel-independent Gaussian weight
        const float nh = sh_nh[0];
        #pragma unroll 4
        for (int i = 0; i < NCHUNK; i++) {
            float dx = xm - shx[i];
            float e  = __expf(dx * dx * nh);
            const float4* rp = reinterpret_cast<const float4*>(shrt[i]);
            float4 r0 = rp[0], r1 = rp[1], r2 = rp[2], r3 = rp[3];
            acc[0]  += e * r0.x;  acc[1]  += e * r0.y;
            acc[2]  += e * r0.z;  acc[3]  += e * r0.w;
            acc[4]  += e * r1.x;  acc[5]  += e * r1.y;
            acc[6]  += e * r1.z;  acc[7]  += e * r1.w;
            acc[8]  += e * r2.x;  acc[9]  += e * r2.y;
            acc[10] += e * r2.z;  acc[11] += e * r2.w;
            acc[12] += e * r3.x;  acc[13] += e * r3.y;
            acc[14] += e * r3.z;  acc[15] += e * r3.w;
        }
    } else {
        // generic path: per-channel length scales
        float nh[Cc];
        #pragma unroll
        for (int c = 0; c < Cc; c++) nh[c] = sh_nh[c];
        #pragma unroll 2
        for (int i = 0; i < NCHUNK; i++) {
            float dx = xm - shx[i];
            float d  = dx * dx;
            #pragma unroll
            for (int c = 0; c < Cc; c++)
                acc[c] += __expf(d * nh[c]) * shrt[i][c];
        }
    }

    float* zp = g_zp + (((size_t)b * NOUT + m) * NSPLIT + s) * Cc;
    #pragma unroll
    for (int c = 0; c < Cc; c += 4)
        *reinterpret_cast<float4*>(zp + c) =
            make_float4(acc[c], acc[c + 1], acc[c + 2], acc[c + 3]);
}

// ---------------------------------------------------------------------------
// Kernel E: reduce NSPLIT partials + pointwise linear C -> OUT_C.
// One thread per (b, m, o).
// ---------------------------------------------------------------------------
__global__ void linear_kernel(const float* __restrict__ lw,
                              const float* __restrict__ lb,
                              float* __restrict__ out) {
    const int tid = blockIdx.x * blockDim.x + threadIdx.x;  // 262144
    const int o   = tid & (OUTC - 1);
    const int bm  = tid >> 5;

    const float* zp = g_zp + (size_t)bm * NSPLIT * Cc;
    float acc = lb[o];
    #pragma unroll
    for (int c = 0; c < Cc; c++) {
        float z = zp[c] + zp[Cc + c] + zp[2 * Cc + c] + zp[3 * Cc + c];
        acc += lw[o * Cc + c] * z;
    }
    out[tid] = acc;
}

// ---------------------------------------------------------------------------
// Launch. Inputs (metadata order):
// 0 r (8,16,512) | 1 x_context (8,512,1) | 2 y_context (unused) |
// 3 x_target (8,1024,1) | 4 conv_w (16,16,5) | 5 conv_b (16) |
// 6 sigma (16) | 7 lin_w (32,16) | 8 lin_b (32)  -> out (8,1024,32) f32
// ---------------------------------------------------------------------------
extern "C" void kernel_launch(void* const* d_in, const int* in_sizes, int n_in,
                              void* d_out, int out_size) {
    const float* r      = (const float*)d_in[0];
    const float* xc     = (const float*)d_in[1];
    const float* xt     = (const float*)d_in[3];
    const float* conv_w = (const float*)d_in[4];
    const float* conv_b = (const float*)d_in[5];
    const float* sigma  = (const float*)d_in[6];
    const float* lin_w  = (const float*)d_in[7];
    const float* lin_b  = (const float*)d_in[8];
    float* out = (float*)d_out;

    conv_kernel<<<dim3(NIN / DTHREADS, Bq), DTHREADS>>>(r, conv_w, conv_b);
    gauss_kernel<<<dim3(MT, NSPLIT, Bq), DTHREADS>>>(xc, xt, sigma);
    linear_kernel<<<(Bq * NOUT * OUTC) / 256, 256>>>(lin_w, lin_b, out);
}

// round 2
// speedup vs baseline: 1.4804x; 1.4804x over previous
#include <cuda_runtime.h>

// Problem constants
#define Bq     8
#define NIN    512
#define NOUT   1024
#define Cc     16
#define OUTC   32
#define KW     5

// Conv tiling
#define CNTILE 64                 // n positions per conv block
#define CTHREADS 256              // 64 n * 4 channel-groups

// Fused gauss+linear tiling
#define MTILE  32                 // m targets per block (== warp lanes)
#define MT     (NOUT / MTILE)     // 32
#define GWARPS 8                  // n-chunks per block
#define NPW    (NIN / GWARPS)     // 64 n per warp
#define GTHREADS (GWARPS * 32)    // 256

// Scratch: conv output, layout [b][n][c] (no runtime allocation allowed)
__device__ float g_rt[Bq * NIN * Cc];

// ---------------------------------------------------------------------------
// Kernel 1: Conv1d (NCH, OIH, SAME pad=2) + bias -> g_rt[b][n][c]
// grid (NIN/CNTILE, B) = (8, 8), block 256.
// thread t: nl = t & 63 (n within tile), cg = t >> 6 (group of 4 out-channels)
// ---------------------------------------------------------------------------
__global__ void conv_kernel(const float* __restrict__ r,
                            const float* __restrict__ w,
                            const float* __restrict__ bias) {
    __shared__ float sr[Cc][CNTILE + 4];            // padded input tile
    __shared__ float sws[Cc * KW * Cc];             // transposed: [ci][k][c_out]
    __shared__ float sb[Cc];

    const int b  = blockIdx.y;
    const int n0 = blockIdx.x * CNTILE;
    const int t  = threadIdx.x;

    // load input tile with halo (zero-padded)
    for (int i = t; i < Cc * (CNTILE + 4); i += CTHREADS) {
        int ci = i / (CNTILE + 4);
        int j  = i % (CNTILE + 4);
        int n  = n0 + j - 2;
        sr[ci][j] = (n >= 0 && n < NIN) ? r[((size_t)b * Cc + ci) * NIN + n] : 0.0f;
    }
    // load + transpose weights: w[c][ci][k] -> sws[(ci*K+k)*Cc + c]
    for (int i = t; i < Cc * Cc * KW; i += CTHREADS) {
        int c  = i / (Cc * KW);
        int rm = i % (Cc * KW);
        int ci = rm / KW;
        int k  = rm % KW;
        sws[(ci * KW + k) * Cc + c] = w[i];
    }
    if (t < Cc) sb[t] = bias[t];
    __syncthreads();

    const int nl = t & (CNTILE - 1);
    const int cg = t >> 6;            // 0..3, handles channels cg*4..cg*4+3

    float4 a;
    a.x = sb[cg * 4 + 0]; a.y = sb[cg * 4 + 1];
    a.z = sb[cg * 4 + 2]; a.w = sb[cg * 4 + 3];

    #pragma unroll
    for (int k = 0; k < KW; k++) {
        #pragma unroll
        for (int ci = 0; ci < Cc; ci++) {
            float v = sr[ci][nl + k];
            float4 wv = *reinterpret_cast<const float4*>(&sws[(ci * KW + k) * Cc + cg * 4]);
            a.x += v * wv.x; a.y += v * wv.y; a.z += v * wv.z; a.w += v * wv.w;
        }
    }

    *reinterpret_cast<float4*>(g_rt + ((size_t)b * NIN + n0 + nl) * Cc + cg * 4) = a;
}

// ---------------------------------------------------------------------------
// Kernel 2: fused Gaussian transform + split-reduce + pointwise linear.
// grid (MT, B) = (32, 8) = 256 blocks, block 256 (8 warps).
// lane = m (32 targets), warp = n-chunk of 64. All hot-loop shared reads are
// warp-broadcast. In-block reduce of 8 partials, then C->OUT_C linear, direct
// coalesced store to out.
// ---------------------------------------------------------------------------
__global__ void gauss_lin_kernel(const float* __restrict__ xc,
                                 const float* __restrict__ xt,
                                 const float* __restrict__ sigma,
                                 const float* __restrict__ lw,
                                 const float* __restrict__ lb,
                                 float* __restrict__ out) {
    __shared__ float shx[NIN];                      // 2 KB
    __shared__ float shrt[NIN][Cc];                 // 32 KB
    __shared__ float red[GWARPS * MTILE * Cc];      // 16 KB partials
    __shared__ float shlw[OUTC * Cc];               // 2 KB
    __shared__ float sh_nh[Cc];
    __shared__ int   sh_alleq;

    const int b  = blockIdx.y;
    const int mt = blockIdx.x;
    const int t  = threadIdx.x;
    const int lane = t & 31;
    const int wid  = t >> 5;

    if (t < Cc) {
        float sg = sigma[t];
        sh_nh[t] = -0.5f * expf(-2.0f * sg);
    }
    if (t == 0) {
        float s0 = sigma[0];
        int eq = 1;
        #pragma unroll
        for (int c = 1; c < Cc; c++) eq &= (sigma[c] == s0);
        sh_alleq = eq;
    }
    for (int i = t; i < NIN; i += GTHREADS) shx[i] = xc[(size_t)b * NIN + i];
    {
        const float4* src = reinterpret_cast<const float4*>(g_rt + (size_t)b * NIN * Cc);
        float4* dst = reinterpret_cast<float4*>(&shrt[0][0]);
        #pragma unroll
        for (int i = t; i < NIN * Cc / 4; i += GTHREADS) dst[i] = src[i];
    }
    for (int i = t; i < OUTC * Cc; i += GTHREADS) shlw[i] = lw[i];
    __syncthreads();

    const int m  = mt * MTILE + lane;
    const float xm = xt[(size_t)b * NOUT + m];

    float acc[Cc];
    #pragma unroll
    for (int c = 0; c < Cc; c++) acc[c] = 0.0f;

    const int n0 = wid * NPW;

    if (sh_alleq) {
        const float nh = sh_nh[0];
        #pragma unroll 4
        for (int i = 0; i < NPW; i++) {
            const int n = n0 + i;
            float dx = xm - shx[n];                 // broadcast LDS
            float e  = __expf(dx * dx * nh);
            const float4* rp = reinterpret_cast<const float4*>(shrt[n]);  // broadcast
            float4 r0 = rp[0], r1 = rp[1], r2 = rp[2], r3 = rp[3];
            acc[0]  += e * r0.x;  acc[1]  += e * r0.y;
            acc[2]  += e * r0.z;  acc[3]  += e * r0.w;
            acc[4]  += e * r1.x;  acc[5]  += e * r1.y;
            acc[6]  += e * r1.z;  acc[7]  += e * r1.w;
            acc[8]  += e * r2.x;  acc[9]  += e * r2.y;
            acc[10] += e * r2.z;  acc[11] += e * r2.w;
            acc[12] += e * r3.x;  acc[13] += e * r3.y;
            acc[14] += e * r3.z;  acc[15] += e * r3.w;
        }
    } else {
        float nh[Cc];
        #pragma unroll
        for (int c = 0; c < Cc; c++) nh[c] = sh_nh[c];
        for (int i = 0; i < NPW; i++) {
            const int n = n0 + i;
            float dx = xm - shx[n];
            float d  = dx * dx;
            #pragma unroll
            for (int c = 0; c < Cc; c++)
                acc[c] += __expf(d * nh[c]) * shrt[n][c];
        }
    }

    // write partials: red[wid][lane][c]
    {
        float* rp = red + ((size_t)wid * MTILE + lane) * Cc;
        #pragma unroll
        for (int c = 0; c < Cc; c += 4)
            *reinterpret_cast<float4*>(rp + c) =
                make_float4(acc[c], acc[c + 1], acc[c + 2], acc[c + 3]);
    }
    __syncthreads();

    // reduce 8 warp-partials into red[0..MTILE*Cc)
    {
        float4* rv = reinterpret_cast<float4*>(red);
        const int NV = MTILE * Cc / 4;              // 128 float4 slots
        if (t < NV) {
            float4 s = rv[t];
            #pragma unroll
            for (int w = 1; w < GWARPS; w++) {
                float4 p = rv[w * NV + t];
                s.x += p.x; s.y += p.y; s.z += p.z; s.w += p.w;
            }
            rv[t] = s;
        }
    }
    __syncthreads();

    // linear C -> OUT_C: thread t handles (m = t>>3, 4 outputs og..og+3)
    {
        const int ml = t >> 3;
        const int og = (t & 7) * 4;
        const float* z = red + ml * Cc;
        float4 o4;
        o4.x = __ldg(lb + og + 0); o4.y = __ldg(lb + og + 1);
        o4.z = __ldg(lb + og + 2); o4.w = __ldg(lb + og + 3);
        #pragma unroll
        for (int c = 0; c < Cc; c++) {
            float zc = z[c];
            o4.x += zc * shlw[(og + 0) * Cc + c];
            o4.y += zc * shlw[(og + 1) * Cc + c];
            o4.z += zc * shlw[(og + 2) * Cc + c];
            o4.w += zc * shlw[(og + 3) * Cc + c];
        }
        *reinterpret_cast<float4*>(
            out + (((size_t)b * NOUT) + mt * MTILE + ml) * OUTC + og) = o4;
    }
}

// ---------------------------------------------------------------------------
// Launch. Inputs (metadata order):
// 0 r (8,16,512) | 1 x_context (8,512,1) | 2 y_context (unused) |
// 3 x_target (8,1024,1) | 4 conv_w (16,16,5) | 5 conv_b (16) |
// 6 sigma (16) | 7 lin_w (32,16) | 8 lin_b (32)  -> out (8,1024,32) f32
// ---------------------------------------------------------------------------
extern "C" void kernel_launch(void* const* d_in, const int* in_sizes, int n_in,
                              void* d_out, int out_size) {
    const float* r      = (const float*)d_in[0];
    const float* xc     = (const float*)d_in[1];
    const float* xt     = (const float*)d_in[3];
    const float* conv_w = (const float*)d_in[4];
    const float* conv_b = (const float*)d_in[5];
    const float* sigma  = (const float*)d_in[6];
    const float* lin_w  = (const float*)d_in[7];
    const float* lin_b  = (const float*)d_in[8];
    float* out = (float*)d_out;

    conv_kernel<<<dim3(NIN / CNTILE, Bq), CTHREADS>>>(r, conv_w, conv_b);
    gauss_lin_kernel<<<dim3(MT, Bq), GTHREADS>>>(xc, xt, sigma, lin_w, lin_b, out);
}

// round 3
// speedup vs baseline: 1.6411x; 1.1085x over previous
#include <cuda_runtime.h>
#include <cstdint>

// Problem constants
#define Bq     8
#define NIN    512
#define NOUT   1024
#define Cc     16
#define OUTC   32
#define KW     5

// Conv tiling
#define CNTILE 64
#define CTHREADS 256

// Fused gauss+linear tiling
#define MTILE  64                 // m targets per block (2 per thread)
#define MT     (NOUT / MTILE)     // 16
#define GWARPS 8
#define NPW    (NIN / GWARPS)     // 64
#define GTHREADS (GWARPS * 32)    // 256

#define LOG2E 1.4426950408889634f

__device__ float g_rt[Bq * NIN * Cc];   // conv output [b][n][c]

__device__ __forceinline__ void ffma2(uint64_t& d, uint64_t a, uint64_t b) {
    asm("fma.rn.f32x2 %0, %1, %2, %0;" : "+l"(d) : "l"(a), "l"(b));
}
__device__ __forceinline__ uint64_t pack2(float lo, float hi) {
    uint64_t r; asm("mov.b64 %0, {%1, %2};" : "=l"(r) : "f"(lo), "f"(hi)); return r;
}
__device__ __forceinline__ void unpack2(uint64_t v, float& lo, float& hi) {
    asm("mov.b64 {%0, %1}, %2;" : "=f"(lo), "=f"(hi) : "l"(v));
}
__device__ __forceinline__ float ex2a(float x) {
    float r; asm("ex2.approx.f32 %0, %1;" : "=f"(r) : "f"(x)); return r;
}

// ---------------------------------------------------------------------------
// Kernel 1: Conv1d (NCH, OIH, SAME pad=2) + bias -> g_rt[b][n][c]
// ---------------------------------------------------------------------------
__global__ void conv_kernel(const float* __restrict__ r,
                            const float* __restrict__ w,
                            const float* __restrict__ bias) {
    __shared__ float sr[Cc][CNTILE + 4];
    __shared__ float sws[Cc * KW * Cc];   // [ci][k][c_out]
    __shared__ float sb[Cc];

    const int b  = blockIdx.y;
    const int n0 = blockIdx.x * CNTILE;
    const int t  = threadIdx.x;

    for (int i = t; i < Cc * (CNTILE + 4); i += CTHREADS) {
        int ci = i / (CNTILE + 4);
        int j  = i % (CNTILE + 4);
        int n  = n0 + j - 2;
        sr[ci][j] = (n >= 0 && n < NIN) ? r[((size_t)b * Cc + ci) * NIN + n] : 0.0f;
    }
    for (int i = t; i < Cc * Cc * KW; i += CTHREADS) {
        int c  = i / (Cc * KW);
        int rm = i % (Cc * KW);
        int ci = rm / KW;
        int k  = rm % KW;
        sws[(ci * KW + k) * Cc + c] = w[i];
    }
    if (t < Cc) sb[t] = bias[t];
    __syncthreads();

    const int nl = t & (CNTILE - 1);
    const int cg = t >> 6;

    float4 a;
    a.x = sb[cg * 4 + 0]; a.y = sb[cg * 4 + 1];
    a.z = sb[cg * 4 + 2]; a.w = sb[cg * 4 + 3];

    #pragma unroll
    for (int k = 0; k < KW; k++) {
        #pragma unroll
        for (int ci = 0; ci < Cc; ci++) {
            float v = sr[ci][nl + k];
            float4 wv = *reinterpret_cast<const float4*>(&sws[(ci * KW + k) * Cc + cg * 4]);
            a.x += v * wv.x; a.y += v * wv.y; a.z += v * wv.z; a.w += v * wv.w;
        }
    }

    *reinterpret_cast<float4*>(g_rt + ((size_t)b * NIN + n0 + nl) * Cc + cg * 4) = a;
}

// ---------------------------------------------------------------------------
// Kernel 2: fused Gaussian transform + reduce + pointwise linear.
// grid (MT, B) = (16, 8), block 256 (8 warps). Warp = n-chunk of 64,
// lane = m-pair {m0 = mt*64+lane, m1 = m0+32}. Packed f32x2 FMA accumulate.
// ---------------------------------------------------------------------------
__global__ void gauss_lin_kernel(const float* __restrict__ xc,
                                 const float* __restrict__ xt,
                                 const float* __restrict__ sigma,
                                 const float* __restrict__ lw,
                                 const float* __restrict__ lb,
                                 float* __restrict__ out) {
    __shared__ float shx[NIN];
    __shared__ __align__(16) float shrt[NIN][Cc];              // 32 KB
    __shared__ __align__(16) float red[GWARPS * MTILE * Cc];   // 32 KB
    __shared__ float shlw[OUTC * Cc];
    __shared__ float sh_nh[Cc];
    __shared__ int   sh_alleq;

    const int b  = blockIdx.y;
    const int mt = blockIdx.x;
    const int t  = threadIdx.x;
    const int lane = t & 31;
    const int wid  = t >> 5;

    if (t < Cc) {
        float sg = sigma[t];
        sh_nh[t] = -0.5f * expf(-2.0f * sg) * LOG2E;  // fold log2e for ex2
    }
    if (t == 0) {
        float s0 = sigma[0];
        int eq = 1;
        #pragma unroll
        for (int c = 1; c < Cc; c++) eq &= (sigma[c] == s0);
        sh_alleq = eq;
    }
    for (int i = t; i < NIN; i += GTHREADS) shx[i] = xc[(size_t)b * NIN + i];
    {
        const float4* src = reinterpret_cast<const float4*>(g_rt + (size_t)b * NIN * Cc);
        float4* dst = reinterpret_cast<float4*>(&shrt[0][0]);
        #pragma unroll
        for (int i = t; i < NIN * Cc / 4; i += GTHREADS) dst[i] = src[i];
    }
    for (int i = t; i < OUTC * Cc; i += GTHREADS) shlw[i] = lw[i];
    __syncthreads();

    const int m0 = mt * MTILE + lane;
    const int m1 = m0 + 32;
    const float xm0 = xt[(size_t)b * NOUT + m0];
    const float xm1 = xt[(size_t)b * NOUT + m1];

    uint64_t a0[8], a1[8];
    #pragma unroll
    for (int p = 0; p < 8; p++) { a0[p] = 0ull; a1[p] = 0ull; }

    const int n0 = wid * NPW;

    if (sh_alleq) {
        const float nh = sh_nh[0];
        #pragma unroll 4
        for (int i = 0; i < NPW; i++) {
            const int n = n0 + i;
            const float xn = shx[n];                              // broadcast
            float d0 = xm0 - xn, d1 = xm1 - xn;
            float e0 = ex2a(d0 * d0 * nh);
            float e1 = ex2a(d1 * d1 * nh);
            uint64_t e0p = pack2(e0, e0);
            uint64_t e1p = pack2(e1, e1);
            const ulonglong2* rp = reinterpret_cast<const ulonglong2*>(shrt[n]);
            ulonglong2 q0 = rp[0], q1 = rp[1], q2 = rp[2], q3 = rp[3];
            ffma2(a0[0], e0p, q0.x); ffma2(a0[1], e0p, q0.y);
            ffma2(a0[2], e0p, q1.x); ffma2(a0[3], e0p, q1.y);
            ffma2(a0[4], e0p, q2.x); ffma2(a0[5], e0p, q2.y);
            ffma2(a0[6], e0p, q3.x); ffma2(a0[7], e0p, q3.y);
            ffma2(a1[0], e1p, q0.x); ffma2(a1[1], e1p, q0.y);
            ffma2(a1[2], e1p, q1.x); ffma2(a1[3], e1p, q1.y);
            ffma2(a1[4], e1p, q2.x); ffma2(a1[5], e1p, q2.y);
            ffma2(a1[6], e1p, q3.x); ffma2(a1[7], e1p, q3.y);
        }
    } else {
        float nh[Cc];
        #pragma unroll
        for (int c = 0; c < Cc; c++) nh[c] = sh_nh[c];
        for (int i = 0; i < NPW; i++) {
            const int n = n0 + i;
            const float xn = shx[n];
            float d0 = (xm0 - xn) * (xm0 - xn);
            float d1 = (xm1 - xn) * (xm1 - xn);
            const ulonglong2* rp = reinterpret_cast<const ulonglong2*>(shrt[n]);
            ulonglong2 q[4] = {rp[0], rp[1], rp[2], rp[3]};
            #pragma unroll
            for (int p = 0; p < 8; p++) {
                uint64_t qv = (p & 1) ? ((const ulonglong2*)q)[p >> 1].y
                                      : ((const ulonglong2*)q)[p >> 1].x;
                uint64_t e0p = pack2(ex2a(d0 * nh[2 * p]), ex2a(d0 * nh[2 * p + 1]));
                uint64_t e1p = pack2(ex2a(d1 * nh[2 * p]), ex2a(d1 * nh[2 * p + 1]));
                ffma2(a0[p], e0p, qv);
                ffma2(a1[p], e1p, qv);
            }
        }
    }

    // write partials: red[wid][ml][c]
    {
        float v[Cc];
        #pragma unroll
        for (int p = 0; p < 8; p++) unpack2(a0[p], v[2 * p], v[2 * p + 1]);
        float* rp0 = red + ((size_t)wid * MTILE + lane) * Cc;
        #pragma unroll
        for (int c = 0; c < Cc; c += 4)
            *reinterpret_cast<float4*>(rp0 + c) =
                make_float4(v[c], v[c + 1], v[c + 2], v[c + 3]);
        #pragma unroll
        for (int p = 0; p < 8; p++) unpack2(a1[p], v[2 * p], v[2 * p + 1]);
        float* rp1 = red + ((size_t)wid * MTILE + lane + 32) * Cc;
        #pragma unroll
        for (int c = 0; c < Cc; c += 4)
            *reinterpret_cast<float4*>(rp1 + c) =
                make_float4(v[c], v[c + 1], v[c + 2], v[c + 3]);
    }
    __syncthreads();

    // reduce 8 warp-partials: red[0..MTILE*Cc) = sum over warps
    {
        float4* rv = reinterpret_cast<float4*>(red);
        const int NV = MTILE * Cc / 4;   // 256 — exactly one per thread
        float4 s = rv[t];
        #pragma unroll
        for (int w = 1; w < GWARPS; w++) {
            float4 p = rv[w * NV + t];
            s.x += p.x; s.y += p.y; s.z += p.z; s.w += p.w;
        }
        __syncthreads();
        rv[t] = s;
    }
    __syncthreads();

    // linear C -> OUT_C: thread t -> (ml = t>>2, 8 outputs at og=(t&3)*8)
    {
        const int ml = t >> 2;
        const int og = (t & 3) * 8;
        const float* z = red + ml * Cc;
        float o[8];
        #pragma unroll
        for (int k = 0; k < 8; k++) o[k] = __ldg(lb + og + k);
        #pragma unroll
        for (int c = 0; c < Cc; c++) {
            float zc = z[c];
            #pragma unroll
            for (int k = 0; k < 8; k++) o[k] += zc * shlw[(og + k) * Cc + c];
        }
        float* op = out + (((size_t)b * NOUT) + mt * MTILE + ml) * OUTC + og;
        *reinterpret_cast<float4*>(op)     = make_float4(o[0], o[1], o[2], o[3]);
        *reinterpret_cast<float4*>(op + 4) = make_float4(o[4], o[5], o[6], o[7]);
    }
}

// ---------------------------------------------------------------------------
// Launch. Inputs (metadata order):
// 0 r (8,16,512) | 1 x_context (8,512,1) | 2 y_context (unused) |
// 3 x_target (8,1024,1) | 4 conv_w (16,16,5) | 5 conv_b (16) |
// 6 sigma (16) | 7 lin_w (32,16) | 8 lin_b (32)  -> out (8,1024,32) f32
// ---------------------------------------------------------------------------
extern "C" void kernel_launch(void* const* d_in, const int* in_sizes, int n_in,
                              void* d_out, int out_size) {
    const float* r      = (const float*)d_in[0];
    const float* xc     = (const float*)d_in[1];
    const float* xt     = (const float*)d_in[3];
    const float* conv_w = (const float*)d_in[4];
    const float* conv_b = (const float*)d_in[5];
    const float* sigma  = (const float*)d_in[6];
    const float* lin_w  = (const float*)d_in[7];
    const float* lin_b  = (const float*)d_in[8];
    float* out = (float*)d_out;

    conv_kernel<<<dim3(NIN / CNTILE, Bq), CTHREADS>>>(r, conv_w, conv_b);
    gauss_lin_kernel<<<dim3(MT, Bq), GTHREADS>>>(xc, xt, sigma, lin_w, lin_b, out);
}